// round 15
// baseline (speedup 1.0000x reference)
#include <cuda_runtime.h>
#include <cuda_bf16.h>

#define Bsz 8
#define Tsz 2048
#define Dsz 64
#define Fsz 128
#define NTILE 32              // Tsz/64 t-chunks per b
#define NBLK (NTILE * Bsz)    // 256 blocks total
#define XP  132               // xs pitch (floats): 16B-multiple, banks shift 4/row
#define LSP 68                // ls pitch (floats)
#define DTP2 65               // dsT2 pitch (u64)
#define WP2  66               // w2 pitch (u64): >=64 entries, 16B-aligned rows

typedef unsigned long long u64;

// ---- scratch (allocation-free: __device__ globals) ----
__device__ float2 g_part[Bsz * Dsz * NTILE];   // per-(b,d,tile) (max, sumexp)
__device__ unsigned int g_bar;                 // monotonic barrier counter (zero-init)

// ---- packed f32x2 helpers ----
__device__ __forceinline__ u64 ffma2(u64 a, u64 b, u64 c) {
    u64 d;
    asm("fma.rn.f32x2 %0, %1, %2, %3;" : "=l"(d) : "l"(a), "l"(b), "l"(c));
    return d;
}
__device__ __forceinline__ u64 pk2(float x, float y) {
    u64 r;
    asm("mov.b64 %0, {%1, %2};" : "=l"(r) : "f"(x), "f"(y));
    return r;
}
__device__ __forceinline__ float2 upk2(u64 v) {
    float2 r;
    asm("mov.b64 {%0, %1}, %2;" : "=f"(r.x), "=f"(r.y) : "l"(v));
    return r;
}

// smem layout (float offsets; all even -> 8B alignment for u64 views)
// dsT2 (phase 1, 64*65 u64 = 8320 fl) and w2 (phase 2, 64*66 u64 = 8448 fl)
// share one region sized for the larger.
#define DT_FLOATS (64 * WP2 * 2)           // 8448
#define XS_OFF   0                         // xs [64 t][XP]
#define DT_OFF   (XS_OFF + 64 * XP)
#define LS_OFF   (DT_OFF + DT_FLOATS)      // ls [64 d][LSP]
#define XN_OFF   (LS_OFF + 64 * LSP)       // [64]
#define DN_OFF   (XN_OFF + 64)             // [64]
#define CS_OFF   (DN_OFF + 64)             // [64]
#define LSE_OFF  (CS_OFF + 64)             // [4]
#define WR_OFF   (LSE_OFF + 4)             // wred float2[8][64] = 1024 floats
#define SM_FLOATS (WR_OFF + 1024)

__global__ void __launch_bounds__(256, 2)
lde_fused(const float* __restrict__ x, const float* __restrict__ dic,
          const float* __restrict__ wei, float* __restrict__ out) {
    extern __shared__ float sm[];
    float*  xs   = sm + XS_OFF;
    u64*    dsT2 = (u64*)(sm + DT_OFF);      // phase 1: [kpair][d] packed dic pairs
    u64*    w2   = (u64*)(sm + DT_OFF);      // phase 2 overlay: [d][t] splatted w
    float*  ls   = sm + LS_OFF;
    float*  xn   = sm + XN_OFF;
    float*  dn   = sm + DN_OFF;
    float*  cs   = sm + CS_OFF;
    float*  lse  = sm + LSE_OFF;
    float2* wred = (float2*)(sm + WR_OFF);   // [warp][d]
    float2* mS   = (float2*)(sm + WR_OFF);   // reused post-barrier: [d] (M, invS)

    const int tid  = threadIdx.x;
    const int lane = tid & 31;
    const int li   = lane & 15;
    const int half = lane >> 4;
    const int warp = tid >> 5;
    const int tile = blockIdx.x;
    const int b    = blockIdx.y;
    const int t0   = tile * 64;

    // ---------------- prologue ----------------
    // x tile -> xs (pitch XP)
    {
        const float4* xg = (const float4*)(x + ((size_t)b * Tsz + t0) * Fsz);
        #pragma unroll
        for (int it = 0; it < 8; it++) {
            int fi = tid + it * 256;               // 2048 float4
            int r = fi >> 5, c = fi & 31;
            *(float4*)(xs + r * XP + c * 4) = xg[fi];
        }
    }
    // dic -> dsT2 [kpair][d] packed u64 (float2-granular gmem reads)
    {
        const float2* dg2 = (const float2*)dic;    // 4096 float2: gi = d*64 + kp
        #pragma unroll
        for (int it = 0; it < 16; it++) {
            int gi = tid + it * 256;
            int d = gi >> 6, kp = gi & 63;
            float2 v = dg2[gi];
            dsT2[kp * DTP2 + d] = pk2(v.x, v.y);
        }
    }
    // lse(wei) on warp 7
    if (warp == 7) {
        float a = wei[lane], bb = wei[lane + 32];
        float m = fmaxf(a, bb);
        #pragma unroll
        for (int off = 16; off > 0; off >>= 1)
            m = fmaxf(m, __shfl_xor_sync(0xffffffffu, m, off));
        float s = __expf(a - m) + __expf(bb - m);
        #pragma unroll
        for (int off = 16; off > 0; off >>= 1)
            s += __shfl_xor_sync(0xffffffffu, s, off);
        if (lane == 0) *lse = m + logf(s);
    }
    // out init by tile==0 blocks (pre-barrier -> ordered before all atomics)
    if (tile == 0) {
        const float4* dg4 = (const float4*)dic;
        float4* og4 = (float4*)(out + (size_t)b * (Dsz * Fsz));
        #pragma unroll
        for (int it = 0; it < 8; it++) {
            int fi = tid + it * 256;
            float4 v = dg4[fi];
            og4[fi] = make_float4(-v.x, -v.y, -v.z, -v.w);
        }
    }
    __syncthreads();

    // xn / dn / cs in parallel thread groups
    if (tid < 64) {
        const float4* xr = (const float4*)(xs + tid * XP);
        float s = 0.f;
        #pragma unroll
        for (int q = 0; q < 32; q++) {
            float4 v = xr[(q + tid) & 31];
            s += v.x * v.x + v.y * v.y + v.z * v.z + v.w * v.w;
        }
        xn[tid] = s;
    } else if (tid < 128) {
        int d = tid - 64;
        const float4* dr = (const float4*)(dic + d * Fsz);
        float s = 0.f;
        #pragma unroll
        for (int q = 0; q < 32; q++) {
            float4 v = dr[q];
            s += v.x * v.x + v.y * v.y + v.z * v.z + v.w * v.w;
        }
        dn[d] = s;
    } else if (tid < 192) {
        int d = tid - 128;
        cs[d] = -(wei[d] - *lse);
    }
    __syncthreads();

    // ---------------- phase 1: dist GEMM ----------------
    // warp owns t rows [8w, 8w+8); lane-half owns t-parity; lane li owns
    // d = li + 16s (s=0..3). acc1[i][s]: t = 8w + 2i + half.
    const int t0w = warp * 8;
    u64 acc1[4][4];
    #pragma unroll
    for (int i = 0; i < 4; i++)
        #pragma unroll
        for (int s = 0; s < 4; s++) acc1[i][s] = 0ull;

    const float* xbase = xs + (t0w + half) * XP;   // rows t0w+half, +2, +4, +6

    #pragma unroll 4
    for (int k = 0; k < 128; k += 4) {
        int kp = k >> 1;
        u64 B0[4], B1[4];
        #pragma unroll
        for (int s = 0; s < 4; s++) {
            B0[s] = dsT2[(kp + 0) * DTP2 + li + 16 * s];   // 16-lane distinct, 2-way bcast
            B1[s] = dsT2[(kp + 1) * DTP2 + li + 16 * s];
        }
        u64 a0[4], a1[4];
        #pragma unroll
        for (int i = 0; i < 4; i++) {
            ulonglong2 av = *(const ulonglong2*)(xbase + i * 2 * XP + k);  // 2-addr bcast
            a0[i] = av.x; a1[i] = av.y;
        }
        #pragma unroll
        for (int i = 0; i < 4; i++)
            #pragma unroll
            for (int s = 0; s < 4; s++) {
                acc1[i][s] = ffma2(a0[i], B0[s], acc1[i][s]);
                acc1[i][s] = ffma2(a1[i], B1[s], acc1[i][s]);
            }
    }

    // epilogue: logits -> ls[d][t], softmax partials
    {
        float xnv[4];
        #pragma unroll
        for (int i = 0; i < 4; i++) xnv[i] = xn[t0w + 2 * i + half];

        #pragma unroll
        for (int s = 0; s < 4; s++) {
            int d = li + 16 * s;
            float cd = cs[d], dnd = dn[d];
            float lv[4];
            float m = -3.4e38f;
            #pragma unroll
            for (int i = 0; i < 4; i++) {
                float2 p = upk2(acc1[i][s]);
                float g = p.x + p.y;
                float d2 = fmaxf(xnv[i] - 2.f * g + dnd, 0.f);
                lv[i] = cd * sqrtf(d2);
                m = fmaxf(m, lv[i]);
            }
            float ssum = 0.f;
            #pragma unroll
            for (int i = 0; i < 4; i++) {
                ssum += __expf(lv[i] - m);
                ls[d * LSP + t0w + 2 * i + half] = lv[i];
            }
            // merge the two t-parity halves (lane ^ 16 holds same d)
            float mo = __shfl_xor_sync(0xffffffffu, m, 16);
            float so = __shfl_xor_sync(0xffffffffu, ssum, 16);
            float M = fmaxf(m, mo);
            ssum = ssum * __expf(m - M) + so * __expf(mo - M);
            if (half == 0) wred[warp * 64 + d] = make_float2(M, ssum);
        }
    }
    __syncthreads();

    // combine 8 warps' partials per d -> g_part
    if (tid < 64) {
        float2 pr = wred[tid];
        float m = pr.x, s = pr.y;
        #pragma unroll
        for (int w = 1; w < 8; w++) {
            float2 p = wred[w * 64 + tid];
            float M = fmaxf(m, p.x);
            s = s * __expf(m - M) + p.y * __expf(p.x - M);
            m = M;
        }
        g_part[(b * Dsz + tid) * NTILE + tile] = make_float2(m, s);
    }
    __threadfence();
    __syncthreads();

    // ---------------- device-wide barrier (monotonic counter) ----------------
    if (tid == 0) {
        unsigned int old = atomicAdd(&g_bar, 1u);
        unsigned int target = (old / (unsigned)NBLK + 1u) * (unsigned)NBLK;
        volatile unsigned int* vb = &g_bar;
        while (*vb < target) __nanosleep(64);
        __threadfence();
    }
    __syncthreads();

    // ---------------- phase 2: output GEMM ----------------
    // combine per-tile partials -> (M, 1/S) per d for this b
    if (tid < 64) {
        const float2* pp = &g_part[(b * Dsz + tid) * NTILE];
        float M = pp[0].x;
        #pragma unroll
        for (int q = 1; q < NTILE; q++) M = fmaxf(M, pp[q].x);
        float S = 0.f;
        #pragma unroll
        for (int q = 0; q < NTILE; q++) { float2 p = pp[q]; S += p.y * __expf(p.x - M); }
        mS[tid] = make_float2(M, 1.f / S);
    }
    __syncthreads();

    // ls -> w2 (splatted {w,w}), overlaying dead dsT2.  w2[d][t], pitch WP2.
    {
        int d = tid >> 2, ts = (tid & 3) * 16;
        float2 ms = mS[d];
        const float* lr = ls + d * LSP + ts;
        u64* wr = w2 + d * WP2 + ts;
        #pragma unroll
        for (int q = 0; q < 16; q++) {
            float w = __expf(lr[q] - ms.x) * ms.y;
            wr[q] = pk2(w, w);
        }
    }
    __syncthreads();

    // GEMM2: warp owns d rows [8w, 8w+8); lane-half owns d-parity;
    // lane li owns f-pairs {li + 16p}. acc2[j][p]: d = 8w + 2j + half.
    u64 acc2[4][4];
    #pragma unroll
    for (int j = 0; j < 4; j++)
        #pragma unroll
        for (int p = 0; p < 4; p++) acc2[j][p] = 0ull;

    const int dw0 = 8 * warp;
    const u64* wbase = w2 + (dw0 + half) * WP2;    // rows dw0+half, +2, +4, +6

    #pragma unroll 4
    for (int t = 0; t < 64; t += 2) {
        u64 w0[4], w1[4];
        #pragma unroll
        for (int j = 0; j < 4; j++) {
            ulonglong2 wv = *(const ulonglong2*)(wbase + j * 2 * WP2 + t);  // 2-addr bcast
            w0[j] = wv.x; w1[j] = wv.y;
        }
        u64 x0[4], x1[4];
        #pragma unroll
        for (int p = 0; p < 4; p++) {
            x0[p] = *(const u64*)(xs + (t + 0) * XP + 2 * (li + 16 * p));   // 2-way bcast
            x1[p] = *(const u64*)(xs + (t + 1) * XP + 2 * (li + 16 * p));
        }
        #pragma unroll
        for (int j = 0; j < 4; j++)
            #pragma unroll
            for (int p = 0; p < 4; p++) {
                acc2[j][p] = ffma2(w0[j], x0[p], acc2[j][p]);
                acc2[j][p] = ffma2(w1[j], x1[p], acc2[j][p]);
            }
    }

    // epilogue: atomic accumulate into out
    {
        float* ob = out + (size_t)b * (Dsz * Fsz);
        #pragma unroll
        for (int j = 0; j < 4; j++) {
            int d = dw0 + 2 * j + half;
            #pragma unroll
            for (int p = 0; p < 4; p++) {
                int f = 2 * (li + 16 * p);
                float2 v = upk2(acc2[j][p]);
                float* o = ob + d * Fsz + f;
                atomicAdd(o,     v.x);
                atomicAdd(o + 1, v.y);
            }
        }
    }
}

// ============================================================
extern "C" void kernel_launch(void* const* d_in, const int* in_sizes, int n_in,
                              void* d_out, int out_size) {
    const float* x   = (const float*)d_in[0];   // (8, 2048, 128)
    const float* dic = (const float*)d_in[1];   // (64, 128)
    const float* wei = (const float*)d_in[2];   // (64,)
    float* out = (float*)d_out;                 // (8, 8192)

    size_t smem = SM_FLOATS * sizeof(float);    // ~88 KB
    cudaFuncSetAttribute(lde_fused, cudaFuncAttributeMaxDynamicSharedMemorySize, (int)smem);
    lde_fused<<<dim3(NTILE, Bsz), 256, smem>>>(x, dic, wei, out);
}